// round 10
// baseline (speedup 1.0000x reference)
#include <cuda_runtime.h>
#include <cuda_bf16.h>
#include <cstdint>

#define N_USERS 200000
#define N_MOVIES 80000
#define NN 280000
#define TILE_M 128
#define NTILES 2188                    // ceil(NN/128)
#define NPAD (NTILES * TILE_M)         // 280064
#define H 64
#define FM 20

typedef unsigned long long ull;

// Scratch (device globals; allocation is forbidden).
__device__ float g_x0[(size_t)NPAD * H];
__device__ float g_x1[(size_t)NPAD * H];
__device__ float g_agg[(size_t)NPAD * H];
__device__ float g_deg[NPAD];

// ---------------- helpers ----------------
__device__ __forceinline__ uint16_t bf16_bits(float x) {
    __nv_bfloat16 b = __float2bfloat16(x);
    return *reinterpret_cast<uint16_t*>(&b);
}
__device__ __forceinline__ float bf16_val(uint16_t u) {
    __nv_bfloat16 b = *reinterpret_cast<__nv_bfloat16*>(&u);
    return __bfloat162float(b);
}
// pack (even k -> low half, odd k -> high half)
__device__ __forceinline__ uint32_t packbf(uint16_t lo, uint16_t hi) {
    return (uint32_t)lo | ((uint32_t)hi << 16);
}
__device__ __forceinline__ void mma_bf16(float* c, uint4 a, uint32_t b0, uint32_t b1) {
    asm volatile(
        "mma.sync.aligned.m16n8k16.row.col.f32.bf16.bf16.f32 "
        "{%0,%1,%2,%3}, {%4,%5,%6,%7}, {%8,%9}, {%0,%1,%2,%3};"
        : "+f"(c[0]), "+f"(c[1]), "+f"(c[2]), "+f"(c[3])
        : "r"(a.x), "r"(a.y), "r"(a.z), "r"(a.w), "r"(b0), "r"(b1));
}

// smem layout (bytes). A-frag: [rtile8][kstep8][lane32][4xb32] = 32KB per term.
// B-frag: [kstep8][chunk4][lane32][4xb32] = 16KB per term (chunk = 2 n-tiles).
#define OFF_BIAS 0
#define OFF_AHI  256
#define OFF_ALO  (OFF_AHI + 32768)
#define OFF_BHI  (OFF_ALO + 32768)
#define OFF_BLO  (OFF_BHI + 16384)
#define SMEM_TOTAL (OFF_BLO + 16384)   // 98560 B -> 2 CTAs/SM

// ---------------- movie feature init ----------------
__global__ void movie_init_kernel(const float* __restrict__ movie_x,
                                  const float* __restrict__ lin_W,
                                  const float* __restrict__ lin_b,
                                  const float* __restrict__ movie_emb,
                                  float* __restrict__ x0) {
    int mlocal = threadIdx.x >> 6;
    int h = threadIdx.x & 63;
    int m = blockIdx.x * 4 + mlocal;
    __shared__ float mx[4][FM];
    int li = threadIdx.x;
    if (li < 4 * FM) {
        int mm = li / FM, ff = li % FM;
        mx[mm][ff] = movie_x[(size_t)(blockIdx.x * 4 + mm) * FM + ff];
    }
    __syncthreads();
    float s = lin_b[h];
#pragma unroll
    for (int f = 0; f < FM; f++) s += mx[mlocal][f] * lin_W[h * FM + f];
    x0[(size_t)(N_USERS + m) * H + h] = s + movie_emb[(size_t)m * H + h];
}

// ---------------- degree count ----------------
__global__ void deg_kernel(const int* __restrict__ dst, float* __restrict__ deg, int E) {
    int e = blockIdx.x * blockDim.x + threadIdx.x;
    if (e < E) atomicAdd(deg + dst[e], 1.0f);
}

// ---------------- scatter: agg[dst] += x[src], vec4 global reductions ----------------
__global__ void scatter_kernel(const int* __restrict__ src,
                               const int* __restrict__ dst,
                               const float* __restrict__ x,
                               float* __restrict__ agg, int E) {
    long long t = (long long)blockIdx.x * blockDim.x + threadIdx.x;
    int e = (int)(t >> 4);
    if (e >= E) return;
    int part = (int)t & 15;
    int s = src[e];
    int d = dst[e];
    float4 v = *reinterpret_cast<const float4*>(x + (size_t)s * H + part * 4);
    float* p = agg + (size_t)d * H + part * 4;
    asm volatile("red.global.add.v4.f32 [%0], {%1,%2,%3,%4};"
                 :: "l"(p), "f"(v.x), "f"(v.y), "f"(v.z), "f"(v.w)
                 : "memory");
}

// ---------------- tensor combine via mma.sync bf16 3-term split ----------------
// xout[m][h] = act( sum_k A[m][k]*W[h][k] + b[h] ),  A=[agg/deg | xin], W=[Wl|Wr], K=128.
// D = Ahi*Bhi + Alo*Bhi + Ahi*Blo  (bf16 hi + bf16 residual lo; error ~2^-17).
// Block: 128 rows, 256 threads = 8 warps; warp w -> rows [w*16, w*16+16), all 64 cols.
template <bool RELU, bool ZERO>
__global__ void __launch_bounds__(256)
combine_mma(const float* __restrict__ xin,
            float* __restrict__ agg,
            const float* __restrict__ deg,
            const float* __restrict__ Wl,
            const float* __restrict__ bias,
            const float* __restrict__ Wr,
            float* __restrict__ xout) {
    extern __shared__ __align__(16) char sm[];
    uint32_t* smw = reinterpret_cast<uint32_t*>(sm);
    int t = threadIdx.x;
    int rowBase = blockIdx.x * TILE_M;

    if (t < 64) reinterpret_cast<float*>(sm + OFF_BIAS)[t] = bias[t];

    // ---- stage B = [Wl | Wr] into bf16 hi/lo fragment order ----
    // FULL B: 64 rows x 128 k = 2048 float4  (R9 bug: only half was staged)
    // element (h,k): kstep=k>>4, kk=k&15, g=h&7, nt=h>>3
    // word w = nt*2 + (kk>>3); chunk=w>>2; lane=g*4+((kk&7)>>1)
#pragma unroll
    for (int j = 0; j < 8; j++) {
        int idx = t + j * 256;            // 2048 float4
        int h = idx >> 5;                 // 0..63
        int k0 = (idx & 31) * 4;          // 0..124
        float4 w4 = (k0 < 64)
            ? *reinterpret_cast<const float4*>(Wl + h * 64 + k0)
            : *reinterpret_cast<const float4*>(Wr + h * 64 + (k0 - 64));
        uint16_t h0 = bf16_bits(w4.x), h1 = bf16_bits(w4.y);
        uint16_t h2 = bf16_bits(w4.z), h3 = bf16_bits(w4.w);
        uint16_t l0 = bf16_bits(w4.x - bf16_val(h0));
        uint16_t l1 = bf16_bits(w4.y - bf16_val(h1));
        uint16_t l2 = bf16_bits(w4.z - bf16_val(h2));
        uint16_t l3 = bf16_bits(w4.w - bf16_val(h3));
        int kstep = k0 >> 4, kk = k0 & 15;
        int g = h & 7, nt = h >> 3;
        int w = nt * 2 + (kk >> 3);
        int lane01 = g * 4 + ((kk & 7) >> 1);
        int i01 = ((kstep * 4 + (w >> 2)) * 32 + lane01) * 4 + (w & 3);
        int i23 = i01 + 4;                // lane01+1, same word slot
        smw[(OFF_BHI >> 2) + i01] = packbf(h0, h1);
        smw[(OFF_BHI >> 2) + i23] = packbf(h2, h3);
        smw[(OFF_BLO >> 2) + i01] = packbf(l0, l1);
        smw[(OFF_BLO >> 2) + i23] = packbf(l2, l3);
    }

    // ---- stage A = [agg/deg | xin] into bf16 hi/lo fragment order ----
    // element (r,k): rtile=r>>4, rr=r&15; reg=(rr>>3)+2*(kk>>3); lane=(rr&7)*4+((kk&7)>>1)
#pragma unroll
    for (int j = 0; j < 16; j++) {
        int idx = t + j * 256;            // 4096 float4
        int r = idx >> 5;
        int q = idx & 31;
        int k0 = q * 4;
        int grow = rowBase + r;
        float4 v;
        if (q < 16) {
            v = *reinterpret_cast<const float4*>(agg + (size_t)grow * H + k0);
            float inv = 1.0f / fmaxf(deg[grow], 1.0f);
            v.x *= inv; v.y *= inv; v.z *= inv; v.w *= inv;
            if (ZERO)
                *reinterpret_cast<float4*>(agg + (size_t)grow * H + k0) =
                    make_float4(0.f, 0.f, 0.f, 0.f);
        } else {
            v = *reinterpret_cast<const float4*>(xin + (size_t)grow * H + (k0 - 64));
        }
        uint16_t h0 = bf16_bits(v.x), h1 = bf16_bits(v.y);
        uint16_t h2 = bf16_bits(v.z), h3 = bf16_bits(v.w);
        uint16_t l0 = bf16_bits(v.x - bf16_val(h0));
        uint16_t l1 = bf16_bits(v.y - bf16_val(h1));
        uint16_t l2 = bf16_bits(v.z - bf16_val(h2));
        uint16_t l3 = bf16_bits(v.w - bf16_val(h3));
        int rtile = r >> 4, rr = r & 15;
        int kstep = k0 >> 4, kk = k0 & 15;
        int reg = (rr >> 3) + 2 * (kk >> 3);
        int lane01 = (rr & 7) * 4 + ((kk & 7) >> 1);
        int i01 = ((rtile * 8 + kstep) * 32 + lane01) * 4 + reg;
        int i23 = i01 + 4;
        smw[(OFF_AHI >> 2) + i01] = packbf(h0, h1);
        smw[(OFF_AHI >> 2) + i23] = packbf(h2, h3);
        smw[(OFF_ALO >> 2) + i01] = packbf(l0, l1);
        smw[(OFF_ALO >> 2) + i23] = packbf(l2, l3);
    }
    __syncthreads();

    // ---- compute ----
    int lane = t & 31, wid = t >> 5;
    float acc[8][4];
#pragma unroll
    for (int n = 0; n < 8; n++)
#pragma unroll
        for (int i = 0; i < 4; i++) acc[n][i] = 0.f;

    const char* aHiB = sm + OFF_AHI + (wid * 8) * 512 + lane * 16;
    const char* aLoB = sm + OFF_ALO + (wid * 8) * 512 + lane * 16;
    const char* bHiB = sm + OFF_BHI + lane * 16;
    const char* bLoB = sm + OFF_BLO + lane * 16;

#pragma unroll
    for (int ks = 0; ks < 8; ks++) {
        uint4 ahi = *reinterpret_cast<const uint4*>(aHiB + ks * 512);
        uint4 alo = *reinterpret_cast<const uint4*>(aLoB + ks * 512);
        uint4 bh[4], bl[4];
#pragma unroll
        for (int c = 0; c < 4; c++) {
            bh[c] = *reinterpret_cast<const uint4*>(bHiB + (ks * 4 + c) * 512);
            bl[c] = *reinterpret_cast<const uint4*>(bLoB + (ks * 4 + c) * 512);
        }
        const uint32_t* bhw = reinterpret_cast<const uint32_t*>(bh);
        const uint32_t* blw = reinterpret_cast<const uint32_t*>(bl);
#pragma unroll
        for (int n = 0; n < 8; n++) {
            uint32_t b0h = bhw[n * 2], b1h = bhw[n * 2 + 1];
            mma_bf16(acc[n], ahi, b0h, b1h);
            mma_bf16(acc[n], alo, b0h, b1h);
            mma_bf16(acc[n], ahi, blw[n * 2], blw[n * 2 + 1]);
        }
    }

    // ---- epilogue: bias + relu + store ----
    int g = lane >> 2, t4 = lane & 3;
    int row0 = rowBase + wid * 16 + g;
    int row1 = row0 + 8;
    const float* bb = reinterpret_cast<const float*>(sm + OFF_BIAS);
#pragma unroll
    for (int n = 0; n < 8; n++) {
        int c = n * 8 + t4 * 2;
        float2 b2 = *reinterpret_cast<const float2*>(bb + c);
        float o0 = acc[n][0] + b2.x, o1 = acc[n][1] + b2.y;
        float o2 = acc[n][2] + b2.x, o3 = acc[n][3] + b2.y;
        if (RELU) {
            o0 = fmaxf(o0, 0.f); o1 = fmaxf(o1, 0.f);
            o2 = fmaxf(o2, 0.f); o3 = fmaxf(o3, 0.f);
        }
        *reinterpret_cast<float2*>(xout + (size_t)row0 * H + c) = make_float2(o0, o1);
        *reinterpret_cast<float2*>(xout + (size_t)row1 * H + c) = make_float2(o2, o3);
    }
}

// ---------------- epilogue: out[e] = dot(x2[u], x2[N_USERS+m]) ----------------
__global__ void edgedot_kernel(const float* __restrict__ x2,
                               const int* __restrict__ lu,
                               const int* __restrict__ lm,
                               float* __restrict__ out, int EL) {
    long long t = (long long)blockIdx.x * blockDim.x + threadIdx.x;
    int e = (int)(t >> 4);
    if (e >= EL) return;
    int part = (int)t & 15;
    int u = lu[e];
    int m = lm[e];
    float4 a = *reinterpret_cast<const float4*>(x2 + (size_t)u * H + part * 4);
    float4 b = *reinterpret_cast<const float4*>(x2 + (size_t)(N_USERS + m) * H + part * 4);
    float s = a.x * b.x + a.y * b.y + a.z * b.z + a.w * b.w;
#pragma unroll
    for (int off = 8; off > 0; off >>= 1)
        s += __shfl_down_sync(0xffffffffu, s, off, 16);
    if (part == 0) out[e] = s;
}

extern "C" void kernel_launch(void* const* d_in, const int* in_sizes, int n_in,
                              void* d_out, int out_size) {
    const float* movie_x   = (const float*)d_in[0];
    const float* user_emb  = (const float*)d_in[1];
    const float* movie_emb = (const float*)d_in[2];
    const float* lin_W     = (const float*)d_in[3];
    const float* lin_b     = (const float*)d_in[4];
    const float* W1l       = (const float*)d_in[5];
    const float* b1        = (const float*)d_in[6];
    const float* W1r       = (const float*)d_in[7];
    const float* W2l       = (const float*)d_in[8];
    const float* b2        = (const float*)d_in[9];
    const float* W2r       = (const float*)d_in[10];
    const int* edge_index  = (const int*)d_in[11];   // int32: JAX x64 disabled
    const int* ell         = (const int*)d_in[12];
    int E  = in_sizes[11] / 2;
    int EL = in_sizes[12] / 2;
    float* out = (float*)d_out;

    float *x0, *x1, *agg, *deg;
    cudaGetSymbolAddress((void**)&x0, g_x0);
    cudaGetSymbolAddress((void**)&x1, g_x1);
    cudaGetSymbolAddress((void**)&agg, g_agg);
    cudaGetSymbolAddress((void**)&deg, g_deg);

    cudaFuncSetAttribute(combine_mma<true, true>,
                         cudaFuncAttributeMaxDynamicSharedMemorySize, SMEM_TOTAL);
    cudaFuncSetAttribute(combine_mma<false, false>,
                         cudaFuncAttributeMaxDynamicSharedMemorySize, SMEM_TOTAL);

    // init
    cudaMemsetAsync(agg, 0, sizeof(float) * (size_t)NN * H);
    cudaMemsetAsync(deg, 0, sizeof(float) * NN);
    cudaMemcpyAsync(x0, user_emb, sizeof(float) * (size_t)N_USERS * H,
                    cudaMemcpyDeviceToDevice);
    movie_init_kernel<<<N_MOVIES / 4, 256>>>(movie_x, lin_W, lin_b, movie_emb, x0);
    deg_kernel<<<(E + 255) / 256, 256>>>(edge_index + E, deg, E);

    long long scat_threads = (long long)E * 16;
    int scat_blocks = (int)((scat_threads + 255) / 256);

    // layer 1
    scatter_kernel<<<scat_blocks, 256>>>(edge_index, edge_index + E, x0, agg, E);
    combine_mma<true, true><<<NTILES, 256, SMEM_TOTAL>>>(x0, agg, deg, W1l, b1, W1r, x1);

    // layer 2 (agg re-zeroed during layer-1 combine staging)
    scatter_kernel<<<scat_blocks, 256>>>(edge_index, edge_index + E, x1, agg, E);
    combine_mma<false, false><<<NTILES, 256, SMEM_TOTAL>>>(x1, agg, deg, W2l, b2, W2r, x0);

    // epilogue
    long long dot_threads = (long long)EL * 16;
    int dot_blocks = (int)((dot_threads + 255) / 256);
    edgedot_kernel<<<dot_blocks, 256>>>(x0, ell, ell + EL, out, EL);
}

// round 11
// speedup vs baseline: 1.7305x; 1.7305x over previous
#include <cuda_runtime.h>
#include <cuda_bf16.h>
#include <cstdint>

#define N_USERS 200000
#define N_MOVIES 80000
#define NN 280000
#define TILE_M 128
#define NTILES 2188                    // ceil(NN/128)
#define NPAD (NTILES * TILE_M)         // 280064
#define H 64
#define FM 20

typedef unsigned long long ull;

// Scratch (device globals; allocation is forbidden).
__device__ float g_x0[(size_t)NPAD * H];
__device__ float g_x1[(size_t)NPAD * H];
__device__ float g_agg[(size_t)NPAD * H];
__device__ float g_deg[NPAD];
// Pre-built B fragments (bf16x2 words, mma.sync m16n8k16 layout), per layer.
// word index = ((ks*4 + chunk)*32 + lane)*4 + slot,  w = nt*2 + (kk>>3) = chunk*4+slot
__device__ uint32_t g_bfhi[2 * 8192];
__device__ uint32_t g_bflo[2 * 8192];

// ---------------- helpers ----------------
__device__ __forceinline__ uint16_t bf16_bits(float x) {
    __nv_bfloat16 b = __float2bfloat16(x);
    return *reinterpret_cast<uint16_t*>(&b);
}
__device__ __forceinline__ float bf16_val(uint16_t u) {
    __nv_bfloat16 b = *reinterpret_cast<__nv_bfloat16*>(&u);
    return __bfloat162float(b);
}
__device__ __forceinline__ uint32_t packbf(uint16_t lo, uint16_t hi) {
    return (uint32_t)lo | ((uint32_t)hi << 16);
}
// Truncation split of two fp32 into packed bf16x2 hi + bf16x2 lo (residual exact pre-trunc).
__device__ __forceinline__ void split2(float2 v, uint32_t& hi, uint32_t& lo) {
    uint32_t bx = __float_as_uint(v.x), by = __float_as_uint(v.y);
    hi = __byte_perm(bx, by, 0x7632);
    float lx = v.x - __uint_as_float(bx & 0xFFFF0000u);
    float ly = v.y - __uint_as_float(by & 0xFFFF0000u);
    lo = __byte_perm(__float_as_uint(lx), __float_as_uint(ly), 0x7632);
}
__device__ __forceinline__ void mma_bf16(float* c, uint4 a, uint32_t b0, uint32_t b1) {
    asm volatile(
        "mma.sync.aligned.m16n8k16.row.col.f32.bf16.bf16.f32 "
        "{%0,%1,%2,%3}, {%4,%5,%6,%7}, {%8,%9}, {%0,%1,%2,%3};"
        : "+f"(c[0]), "+f"(c[1]), "+f"(c[2]), "+f"(c[3])
        : "r"(a.x), "r"(a.y), "r"(a.z), "r"(a.w), "r"(b0), "r"(b1));
}

// ---------------- B fragment prep (once per launch; W is tiny) ----------------
__global__ void prep_bfrag(const float* __restrict__ W1l, const float* __restrict__ W1r,
                           const float* __restrict__ W2l, const float* __restrict__ W2r) {
    int layer = blockIdx.x;
    const float* Wl = layer ? W2l : W1l;
    const float* Wr = layer ? W2r : W1r;
    uint32_t* BH = g_bfhi + layer * 8192;
    uint32_t* BL = g_bflo + layer * 8192;
    int t = threadIdx.x;
#pragma unroll
    for (int j = 0; j < 8; j++) {
        int idx = t + j * 256;            // 2048 float4 over (h, k)
        int h = idx >> 5;                 // 0..63
        int k0 = (idx & 31) * 4;          // 0..124
        float4 w4 = (k0 < 64)
            ? *reinterpret_cast<const float4*>(Wl + h * 64 + k0)
            : *reinterpret_cast<const float4*>(Wr + h * 64 + (k0 - 64));
        uint16_t h0 = bf16_bits(w4.x), h1 = bf16_bits(w4.y);
        uint16_t h2 = bf16_bits(w4.z), h3 = bf16_bits(w4.w);
        uint16_t l0 = bf16_bits(w4.x - bf16_val(h0));
        uint16_t l1 = bf16_bits(w4.y - bf16_val(h1));
        uint16_t l2 = bf16_bits(w4.z - bf16_val(h2));
        uint16_t l3 = bf16_bits(w4.w - bf16_val(h3));
        int kstep = k0 >> 4, kk = k0 & 15;
        int g = h & 7, nt = h >> 3;
        int w = nt * 2 + (kk >> 3);
        int lane01 = g * 4 + ((kk & 7) >> 1);
        int i01 = ((kstep * 4 + (w >> 2)) * 32 + lane01) * 4 + (w & 3);
        int i23 = i01 + 4;
        BH[i01] = packbf(h0, h1); BH[i23] = packbf(h2, h3);
        BL[i01] = packbf(l0, l1); BL[i23] = packbf(l2, l3);
    }
}

// ---------------- movie feature init ----------------
__global__ void movie_init_kernel(const float* __restrict__ movie_x,
                                  const float* __restrict__ lin_W,
                                  const float* __restrict__ lin_b,
                                  const float* __restrict__ movie_emb,
                                  float* __restrict__ x0) {
    int mlocal = threadIdx.x >> 6;
    int h = threadIdx.x & 63;
    int m = blockIdx.x * 4 + mlocal;
    __shared__ float mx[4][FM];
    int li = threadIdx.x;
    if (li < 4 * FM) {
        int mm = li / FM, ff = li % FM;
        mx[mm][ff] = movie_x[(size_t)(blockIdx.x * 4 + mm) * FM + ff];
    }
    __syncthreads();
    float s = lin_b[h];
#pragma unroll
    for (int f = 0; f < FM; f++) s += mx[mlocal][f] * lin_W[h * FM + f];
    x0[(size_t)(N_USERS + m) * H + h] = s + movie_emb[(size_t)m * H + h];
}

// ---------------- degree count ----------------
__global__ void deg_kernel(const int* __restrict__ dst, float* __restrict__ deg, int E) {
    int e = blockIdx.x * blockDim.x + threadIdx.x;
    if (e < E) atomicAdd(deg + dst[e], 1.0f);
}

// ---------------- scatter: agg[dst] += x[src], vec4 global reductions ----------------
__global__ void scatter_kernel(const int* __restrict__ src,
                               const int* __restrict__ dst,
                               const float* __restrict__ x,
                               float* __restrict__ agg, int E) {
    long long t = (long long)blockIdx.x * blockDim.x + threadIdx.x;
    int e = (int)(t >> 4);
    if (e >= E) return;
    int part = (int)t & 15;
    int s = src[e];
    int d = dst[e];
    float4 v = *reinterpret_cast<const float4*>(x + (size_t)s * H + part * 4);
    float* p = agg + (size_t)d * H + part * 4;
    asm volatile("red.global.add.v4.f32 [%0], {%1,%2,%3,%4};"
                 :: "l"(p), "f"(v.x), "f"(v.y), "f"(v.z), "f"(v.w)
                 : "memory");
}

// ---------------- combine: register-direct mma.sync, no smem staging ----------------
// xout[m][h] = act( mean[m]·Wl[h] + xin[m]·Wr[h] + b[h] ), via A=[agg*invd | xin], K=128.
// 3-term bf16 split: D = AhiBhi + AloBhi + AhiBlo. A frags built in registers from
// coalesced LDG.64; B frags pre-built in global (L1-resident).
template <bool RELU, bool ZERO>
__global__ void __launch_bounds__(256)
combine_mma(const float* __restrict__ xin,
            float* __restrict__ agg,
            const float* __restrict__ deg,
            const uint32_t* __restrict__ BH,
            const uint32_t* __restrict__ BL,
            const float* __restrict__ bias,
            float* __restrict__ xout) {
    int t = threadIdx.x;
    int lane = t & 31, wid = t >> 5;
    int g = lane >> 2, t4 = lane & 3;
    int row0 = blockIdx.x * TILE_M + wid * 16 + g;   // rows (g, g+8) of this warp's m16 tile
    int row1 = row0 + 8;

    float invd0 = 1.0f / fmaxf(deg[row0], 1.0f);
    float invd1 = 1.0f / fmaxf(deg[row1], 1.0f);

    float acc[8][4];
#pragma unroll
    for (int n = 0; n < 8; n++)
#pragma unroll
        for (int i = 0; i < 4; i++) acc[n][i] = 0.f;

#pragma unroll
    for (int ks = 0; ks < 8; ks++) {
        int c0 = ks * 16 + t4 * 2;                    // A column of this thread's first pair
        const float* Abase;
        int cc;
        if (ks < 4) { Abase = agg; cc = c0; }
        else        { Abase = xin; cc = c0 - 64; }
        const float* p00 = Abase + (size_t)row0 * H + cc;
        const float* p10 = Abase + (size_t)row1 * H + cc;
        float2 v00 = *reinterpret_cast<const float2*>(p00);
        float2 v01 = *reinterpret_cast<const float2*>(p00 + 8);
        float2 v10 = *reinterpret_cast<const float2*>(p10);
        float2 v11 = *reinterpret_cast<const float2*>(p10 + 8);

        // B fragments for this k-step (hi & lo), 4 chunks each = 16 words
        const uint4* bh4 = reinterpret_cast<const uint4*>(BH) + (size_t)(ks * 4) * 32 + lane;
        const uint4* bl4 = reinterpret_cast<const uint4*>(BL) + (size_t)(ks * 4) * 32 + lane;
        uint4 bh[4], bl[4];
#pragma unroll
        for (int c = 0; c < 4; c++) { bh[c] = bh4[c * 32]; bl[c] = bl4[c * 32]; }

        if (ks < 4) {
            v00.x *= invd0; v00.y *= invd0; v01.x *= invd0; v01.y *= invd0;
            v10.x *= invd1; v10.y *= invd1; v11.x *= invd1; v11.y *= invd1;
            if (ZERO) {
                float2 z = make_float2(0.f, 0.f);
                *reinterpret_cast<float2*>(const_cast<float*>(p00)) = z;
                *reinterpret_cast<float2*>(const_cast<float*>(p00 + 8)) = z;
                *reinterpret_cast<float2*>(const_cast<float*>(p10)) = z;
                *reinterpret_cast<float2*>(const_cast<float*>(p10 + 8)) = z;
            }
        }

        uint4 ahi, alo;
        split2(v00, ahi.x, alo.x);    // a0: (row g,  k pair t4*2)
        split2(v10, ahi.y, alo.y);    // a1: (row g+8, pair t4*2)
        split2(v01, ahi.z, alo.z);    // a2: (row g,  pair t4*2+8)
        split2(v11, ahi.w, alo.w);    // a3: (row g+8, pair t4*2+8)

        const uint32_t* bhw = reinterpret_cast<const uint32_t*>(bh);
        const uint32_t* blw = reinterpret_cast<const uint32_t*>(bl);
#pragma unroll
        for (int n = 0; n < 8; n++) {
            uint32_t b0h = bhw[n * 2], b1h = bhw[n * 2 + 1];
            mma_bf16(acc[n], ahi, b0h, b1h);
            mma_bf16(acc[n], alo, b0h, b1h);
            mma_bf16(acc[n], ahi, blw[n * 2], blw[n * 2 + 1]);
        }
    }

    // ---- epilogue: bias + relu + store ----
#pragma unroll
    for (int n = 0; n < 8; n++) {
        int c = n * 8 + t4 * 2;
        float2 b2 = *reinterpret_cast<const float2*>(bias + c);
        float o0 = acc[n][0] + b2.x, o1 = acc[n][1] + b2.y;
        float o2 = acc[n][2] + b2.x, o3 = acc[n][3] + b2.y;
        if (RELU) {
            o0 = fmaxf(o0, 0.f); o1 = fmaxf(o1, 0.f);
            o2 = fmaxf(o2, 0.f); o3 = fmaxf(o3, 0.f);
        }
        if (row0 < NN)
            *reinterpret_cast<float2*>(xout + (size_t)row0 * H + c) = make_float2(o0, o1);
        if (row1 < NN)
            *reinterpret_cast<float2*>(xout + (size_t)row1 * H + c) = make_float2(o2, o3);
    }
}

// ---------------- epilogue: out[e] = dot(x2[u], x2[N_USERS+m]) ----------------
__global__ void edgedot_kernel(const float* __restrict__ x2,
                               const int* __restrict__ lu,
                               const int* __restrict__ lm,
                               float* __restrict__ out, int EL) {
    long long t = (long long)blockIdx.x * blockDim.x + threadIdx.x;
    int e = (int)(t >> 4);
    if (e >= EL) return;
    int part = (int)t & 15;
    int u = lu[e];
    int m = lm[e];
    float4 a = *reinterpret_cast<const float4*>(x2 + (size_t)u * H + part * 4);
    float4 b = *reinterpret_cast<const float4*>(x2 + (size_t)(N_USERS + m) * H + part * 4);
    float s = a.x * b.x + a.y * b.y + a.z * b.z + a.w * b.w;
#pragma unroll
    for (int off = 8; off > 0; off >>= 1)
        s += __shfl_down_sync(0xffffffffu, s, off, 16);
    if (part == 0) out[e] = s;
}

extern "C" void kernel_launch(void* const* d_in, const int* in_sizes, int n_in,
                              void* d_out, int out_size) {
    const float* movie_x   = (const float*)d_in[0];
    const float* user_emb  = (const float*)d_in[1];
    const float* movie_emb = (const float*)d_in[2];
    const float* lin_W     = (const float*)d_in[3];
    const float* lin_b     = (const float*)d_in[4];
    const float* W1l       = (const float*)d_in[5];
    const float* b1        = (const float*)d_in[6];
    const float* W1r       = (const float*)d_in[7];
    const float* W2l       = (const float*)d_in[8];
    const float* b2        = (const float*)d_in[9];
    const float* W2r       = (const float*)d_in[10];
    const int* edge_index  = (const int*)d_in[11];   // int32: JAX x64 disabled
    const int* ell         = (const int*)d_in[12];
    int E  = in_sizes[11] / 2;
    int EL = in_sizes[12] / 2;
    float* out = (float*)d_out;

    float *x0, *x1, *agg, *deg;
    uint32_t *bfh, *bfl;
    cudaGetSymbolAddress((void**)&x0, g_x0);
    cudaGetSymbolAddress((void**)&x1, g_x1);
    cudaGetSymbolAddress((void**)&agg, g_agg);
    cudaGetSymbolAddress((void**)&deg, g_deg);
    cudaGetSymbolAddress((void**)&bfh, g_bfhi);
    cudaGetSymbolAddress((void**)&bfl, g_bflo);

    // init (zero padded region too: keeps padded-row math finite & deterministic)
    cudaMemsetAsync(agg, 0, sizeof(float) * (size_t)NPAD * H);
    cudaMemsetAsync(deg, 0, sizeof(float) * NPAD);
    cudaMemcpyAsync(x0, user_emb, sizeof(float) * (size_t)N_USERS * H,
                    cudaMemcpyDeviceToDevice);
    movie_init_kernel<<<N_MOVIES / 4, 256>>>(movie_x, lin_W, lin_b, movie_emb, x0);
    prep_bfrag<<<2, 256>>>(W1l, W1r, W2l, W2r);
    deg_kernel<<<(E + 255) / 256, 256>>>(edge_index + E, deg, E);

    long long scat_threads = (long long)E * 16;
    int scat_blocks = (int)((scat_threads + 255) / 256);

    // layer 1
    scatter_kernel<<<scat_blocks, 256>>>(edge_index, edge_index + E, x0, agg, E);
    combine_mma<true, true><<<NTILES, 256>>>(x0, agg, deg, bfh, bfl, b1, x1);

    // layer 2 (agg re-zeroed inside layer-1 combine)
    scatter_kernel<<<scat_blocks, 256>>>(edge_index, edge_index + E, x1, agg, E);
    combine_mma<false, false><<<NTILES, 256>>>(x1, agg, deg, bfh + 8192, bfl + 8192, b2, x0);

    // epilogue
    long long dot_threads = (long long)EL * 16;
    int dot_blocks = (int)((dot_threads + 255) / 256);
    edgedot_kernel<<<dot_blocks, 256>>>(x0, ell, ell + EL, out, EL);
}

// round 12
// speedup vs baseline: 2.2221x; 1.2841x over previous
#include <cuda_runtime.h>
#include <cuda_bf16.h>
#include <cstdint>

#define N_USERS 200000
#define N_MOVIES 80000
#define NN 280000
#define TILE_M 128
#define NTILES 2188                    // ceil(NN/128)
#define NPAD (NTILES * TILE_M)         // 280064
#define H 64
#define FM 20
#define EMAX 1310720                   // >= E (1250000)

#define SCAN_BS 256
#define SCAN_IT 8
#define SCAN_CHUNK (SCAN_BS * SCAN_IT)             // 2048
#define NBLK ((NPAD + SCAN_CHUNK - 1) / SCAN_CHUNK) // 137

typedef unsigned long long ull;

// Scratch (device globals; allocation is forbidden).
__device__ float g_x0[(size_t)NPAD * H];
__device__ float g_x1[(size_t)NPAD * H];
__device__ float g_mean[(size_t)NPAD * H];
__device__ int g_cnt[NPAD];
__device__ int g_off[NPAD + 1];
__device__ int g_cur[NPAD];
__device__ int g_bsum[NBLK];
__device__ int g_csr[EMAX];
// Pre-built B fragments (bf16x2 words, mma.sync m16n8k16 layout), per layer.
__device__ uint32_t g_bfhi[2 * 8192];
__device__ uint32_t g_bflo[2 * 8192];

// ---------------- helpers ----------------
__device__ __forceinline__ uint16_t bf16_bits(float x) {
    __nv_bfloat16 b = __float2bfloat16(x);
    return *reinterpret_cast<uint16_t*>(&b);
}
__device__ __forceinline__ float bf16_val(uint16_t u) {
    __nv_bfloat16 b = *reinterpret_cast<__nv_bfloat16*>(&u);
    return __bfloat162float(b);
}
__device__ __forceinline__ uint32_t packbf(uint16_t lo, uint16_t hi) {
    return (uint32_t)lo | ((uint32_t)hi << 16);
}
// Truncation split of two fp32 into packed bf16x2 hi + bf16x2 lo.
__device__ __forceinline__ void split2(float2 v, uint32_t& hi, uint32_t& lo) {
    uint32_t bx = __float_as_uint(v.x), by = __float_as_uint(v.y);
    hi = __byte_perm(bx, by, 0x7632);
    float lx = v.x - __uint_as_float(bx & 0xFFFF0000u);
    float ly = v.y - __uint_as_float(by & 0xFFFF0000u);
    lo = __byte_perm(__float_as_uint(lx), __float_as_uint(ly), 0x7632);
}
__device__ __forceinline__ void mma_bf16(float* c, uint4 a, uint32_t b0, uint32_t b1) {
    asm volatile(
        "mma.sync.aligned.m16n8k16.row.col.f32.bf16.bf16.f32 "
        "{%0,%1,%2,%3}, {%4,%5,%6,%7}, {%8,%9}, {%0,%1,%2,%3};"
        : "+f"(c[0]), "+f"(c[1]), "+f"(c[2]), "+f"(c[3])
        : "r"(a.x), "r"(a.y), "r"(a.z), "r"(a.w), "r"(b0), "r"(b1));
}

// ---------------- B fragment prep ----------------
__global__ void prep_bfrag(const float* __restrict__ W1l, const float* __restrict__ W1r,
                           const float* __restrict__ W2l, const float* __restrict__ W2r) {
    int layer = blockIdx.x;
    const float* Wl = layer ? W2l : W1l;
    const float* Wr = layer ? W2r : W1r;
    uint32_t* BH = g_bfhi + layer * 8192;
    uint32_t* BL = g_bflo + layer * 8192;
    int t = threadIdx.x;
#pragma unroll
    for (int j = 0; j < 8; j++) {
        int idx = t + j * 256;
        int h = idx >> 5;
        int k0 = (idx & 31) * 4;
        float4 w4 = (k0 < 64)
            ? *reinterpret_cast<const float4*>(Wl + h * 64 + k0)
            : *reinterpret_cast<const float4*>(Wr + h * 64 + (k0 - 64));
        uint16_t h0 = bf16_bits(w4.x), h1 = bf16_bits(w4.y);
        uint16_t h2 = bf16_bits(w4.z), h3 = bf16_bits(w4.w);
        uint16_t l0 = bf16_bits(w4.x - bf16_val(h0));
        uint16_t l1 = bf16_bits(w4.y - bf16_val(h1));
        uint16_t l2 = bf16_bits(w4.z - bf16_val(h2));
        uint16_t l3 = bf16_bits(w4.w - bf16_val(h3));
        int kstep = k0 >> 4, kk = k0 & 15;
        int g = h & 7, nt = h >> 3;
        int w = nt * 2 + (kk >> 3);
        int lane01 = g * 4 + ((kk & 7) >> 1);
        int i01 = ((kstep * 4 + (w >> 2)) * 32 + lane01) * 4 + (w & 3);
        int i23 = i01 + 4;
        BH[i01] = packbf(h0, h1); BH[i23] = packbf(h2, h3);
        BL[i01] = packbf(l0, l1); BL[i23] = packbf(l2, l3);
    }
}

// ---------------- movie feature init ----------------
__global__ void movie_init_kernel(const float* __restrict__ movie_x,
                                  const float* __restrict__ lin_W,
                                  const float* __restrict__ lin_b,
                                  const float* __restrict__ movie_emb,
                                  float* __restrict__ x0) {
    int mlocal = threadIdx.x >> 6;
    int h = threadIdx.x & 63;
    int m = blockIdx.x * 4 + mlocal;
    __shared__ float mx[4][FM];
    int li = threadIdx.x;
    if (li < 4 * FM) {
        int mm = li / FM, ff = li % FM;
        mx[mm][ff] = movie_x[(size_t)(blockIdx.x * 4 + mm) * FM + ff];
    }
    __syncthreads();
    float s = lin_b[h];
#pragma unroll
    for (int f = 0; f < FM; f++) s += mx[mlocal][f] * lin_W[h * FM + f];
    x0[(size_t)(N_USERS + m) * H + h] = s + movie_emb[(size_t)m * H + h];
}

// ---------------- CSR build ----------------
__global__ void hist_kernel(const int* __restrict__ dst, int E) {
    int e = blockIdx.x * blockDim.x + threadIdx.x;
    if (e < E) atomicAdd(g_cnt + dst[e], 1);
}

__global__ void scan1_kernel() {
    __shared__ int sh[SCAN_BS];
    int b = blockIdx.x, t = threadIdx.x;
    int base = b * SCAN_CHUNK + t * SCAN_IT;
    int v[SCAN_IT];
    int tot = 0;
#pragma unroll
    for (int i = 0; i < SCAN_IT; i++) {
        int idx = base + i;
        v[i] = (idx < NPAD) ? g_cnt[idx] : 0;
        tot += v[i];
    }
    sh[t] = tot;
    __syncthreads();
    for (int off = 1; off < SCAN_BS; off <<= 1) {
        int val = (t >= off) ? sh[t - off] : 0;
        __syncthreads();
        sh[t] += val;
        __syncthreads();
    }
    int run = sh[t] - tot;   // exclusive prefix of this thread within block
#pragma unroll
    for (int i = 0; i < SCAN_IT; i++) {
        int idx = base + i;
        if (idx < NPAD) g_off[idx] = run;
        run += v[i];
    }
    if (t == SCAN_BS - 1) g_bsum[b] = sh[t];
}

__global__ void scan2_kernel() {
    __shared__ int sh[SCAN_BS];
    int t = threadIdx.x;
    int v = (t < NBLK) ? g_bsum[t] : 0;
    sh[t] = v;
    __syncthreads();
    for (int off = 1; off < SCAN_BS; off <<= 1) {
        int val = (t >= off) ? sh[t - off] : 0;
        __syncthreads();
        sh[t] += val;
        __syncthreads();
    }
    if (t < NBLK) g_bsum[t] = sh[t] - v;   // exclusive
}

__global__ void scan3_kernel(int E) {
    int i = blockIdx.x * blockDim.x + threadIdx.x;   // grid covers NPAD exactly
    int o = g_off[i] + g_bsum[i / SCAN_CHUNK];
    g_off[i] = o;
    g_cur[i] = o;
    if (i == 0) g_off[NPAD] = E;
}

__global__ void fill_kernel(const int* __restrict__ src, const int* __restrict__ dst, int E) {
    int e = blockIdx.x * blockDim.x + threadIdx.x;
    if (e >= E) return;
    int pos = atomicAdd(g_cur + dst[e], 1);
    g_csr[pos] = src[e];
}

// ---------------- gather: mean[n] = (1/max(deg,1)) * sum_{e in CSR[n]} x[src[e]] ----------
__global__ void __launch_bounds__(256)
gather_mean(const float* __restrict__ x, float* __restrict__ mean) {
    int t = threadIdx.x;
    int node = blockIdx.x * 16 + (t >> 4);
    int part = t & 15;
    int o0 = g_off[node], o1 = g_off[node + 1];
    float4 acc = make_float4(0.f, 0.f, 0.f, 0.f);
    for (int e = o0; e < o1; e++) {
        int s = g_csr[e];                     // broadcast across the 16 lanes
        float4 v = *reinterpret_cast<const float4*>(x + (size_t)s * H + part * 4);
        acc.x += v.x; acc.y += v.y; acc.z += v.z; acc.w += v.w;
    }
    float inv = 1.0f / fmaxf((float)(o1 - o0), 1.0f);
    acc.x *= inv; acc.y *= inv; acc.z *= inv; acc.w *= inv;
    *reinterpret_cast<float4*>(mean + (size_t)node * H + part * 4) = acc;
}

// ---------------- combine: register-direct mma.sync ----------------
// xout[m][h] = act( [mean | xin][m] · [Wl|Wr][h] + b[h] ), K=128.
// 3-term bf16 split: D = AhiBhi + AloBhi + AhiBlo.
template <bool RELU>
__global__ void __launch_bounds__(256)
combine_mma(const float* __restrict__ xin,
            const float* __restrict__ mean,
            const uint32_t* __restrict__ BH,
            const uint32_t* __restrict__ BL,
            const float* __restrict__ bias,
            float* __restrict__ xout) {
    int t = threadIdx.x;
    int lane = t & 31, wid = t >> 5;
    int g = lane >> 2, t4 = lane & 3;
    int row0 = blockIdx.x * TILE_M + wid * 16 + g;
    int row1 = row0 + 8;

    float acc[8][4];
#pragma unroll
    for (int n = 0; n < 8; n++)
#pragma unroll
        for (int i = 0; i < 4; i++) acc[n][i] = 0.f;

#pragma unroll
    for (int ks = 0; ks < 8; ks++) {
        int c0 = ks * 16 + t4 * 2;
        const float* Abase = (ks < 4) ? mean : xin;
        int cc = (ks < 4) ? c0 : c0 - 64;
        const float* p00 = Abase + (size_t)row0 * H + cc;
        const float* p10 = Abase + (size_t)row1 * H + cc;
        float2 v00 = *reinterpret_cast<const float2*>(p00);
        float2 v01 = *reinterpret_cast<const float2*>(p00 + 8);
        float2 v10 = *reinterpret_cast<const float2*>(p10);
        float2 v11 = *reinterpret_cast<const float2*>(p10 + 8);

        const uint4* bh4 = reinterpret_cast<const uint4*>(BH) + (size_t)(ks * 4) * 32 + lane;
        const uint4* bl4 = reinterpret_cast<const uint4*>(BL) + (size_t)(ks * 4) * 32 + lane;
        uint4 bh[4], bl[4];
#pragma unroll
        for (int c = 0; c < 4; c++) { bh[c] = bh4[c * 32]; bl[c] = bl4[c * 32]; }

        uint4 ahi, alo;
        split2(v00, ahi.x, alo.x);
        split2(v10, ahi.y, alo.y);
        split2(v01, ahi.z, alo.z);
        split2(v11, ahi.w, alo.w);

        const uint32_t* bhw = reinterpret_cast<const uint32_t*>(bh);
        const uint32_t* blw = reinterpret_cast<const uint32_t*>(bl);
#pragma unroll
        for (int n = 0; n < 8; n++) {
            uint32_t b0h = bhw[n * 2], b1h = bhw[n * 2 + 1];
            mma_bf16(acc[n], ahi, b0h, b1h);
            mma_bf16(acc[n], alo, b0h, b1h);
            mma_bf16(acc[n], ahi, blw[n * 2], blw[n * 2 + 1]);
        }
    }

#pragma unroll
    for (int n = 0; n < 8; n++) {
        int c = n * 8 + t4 * 2;
        float2 b2 = *reinterpret_cast<const float2*>(bias + c);
        float o0 = acc[n][0] + b2.x, o1 = acc[n][1] + b2.y;
        float o2 = acc[n][2] + b2.x, o3 = acc[n][3] + b2.y;
        if (RELU) {
            o0 = fmaxf(o0, 0.f); o1 = fmaxf(o1, 0.f);
            o2 = fmaxf(o2, 0.f); o3 = fmaxf(o3, 0.f);
        }
        if (row0 < NN)
            *reinterpret_cast<float2*>(xout + (size_t)row0 * H + c) = make_float2(o0, o1);
        if (row1 < NN)
            *reinterpret_cast<float2*>(xout + (size_t)row1 * H + c) = make_float2(o2, o3);
    }
}

// ---------------- epilogue: out[e] = dot(x2[u], x2[N_USERS+m]) ----------------
__global__ void edgedot_kernel(const float* __restrict__ x2,
                               const int* __restrict__ lu,
                               const int* __restrict__ lm,
                               float* __restrict__ out, int EL) {
    long long t = (long long)blockIdx.x * blockDim.x + threadIdx.x;
    int e = (int)(t >> 4);
    if (e >= EL) return;
    int part = (int)t & 15;
    int u = lu[e];
    int m = lm[e];
    float4 a = *reinterpret_cast<const float4*>(x2 + (size_t)u * H + part * 4);
    float4 b = *reinterpret_cast<const float4*>(x2 + (size_t)(N_USERS + m) * H + part * 4);
    float s = a.x * b.x + a.y * b.y + a.z * b.z + a.w * b.w;
#pragma unroll
    for (int off = 8; off > 0; off >>= 1)
        s += __shfl_down_sync(0xffffffffu, s, off, 16);
    if (part == 0) out[e] = s;
}

extern "C" void kernel_launch(void* const* d_in, const int* in_sizes, int n_in,
                              void* d_out, int out_size) {
    const float* movie_x   = (const float*)d_in[0];
    const float* user_emb  = (const float*)d_in[1];
    const float* movie_emb = (const float*)d_in[2];
    const float* lin_W     = (const float*)d_in[3];
    const float* lin_b     = (const float*)d_in[4];
    const float* W1l       = (const float*)d_in[5];
    const float* b1        = (const float*)d_in[6];
    const float* W1r       = (const float*)d_in[7];
    const float* W2l       = (const float*)d_in[8];
    const float* b2        = (const float*)d_in[9];
    const float* W2r       = (const float*)d_in[10];
    const int* edge_index  = (const int*)d_in[11];   // int32: JAX x64 disabled
    const int* ell         = (const int*)d_in[12];
    int E  = in_sizes[11] / 2;
    int EL = in_sizes[12] / 2;
    float* out = (float*)d_out;

    float *x0, *x1, *mean;
    int *cnt;
    uint32_t *bfh, *bfl;
    cudaGetSymbolAddress((void**)&x0, g_x0);
    cudaGetSymbolAddress((void**)&x1, g_x1);
    cudaGetSymbolAddress((void**)&mean, g_mean);
    cudaGetSymbolAddress((void**)&cnt, g_cnt);
    cudaGetSymbolAddress((void**)&bfh, g_bfhi);
    cudaGetSymbolAddress((void**)&bfl, g_bflo);

    const int* esrc = edge_index;
    const int* edst = edge_index + E;

    // init + CSR build
    cudaMemsetAsync(cnt, 0, sizeof(int) * NPAD);
    cudaMemcpyAsync(x0, user_emb, sizeof(float) * (size_t)N_USERS * H,
                    cudaMemcpyDeviceToDevice);
    movie_init_kernel<<<N_MOVIES / 4, 256>>>(movie_x, lin_W, lin_b, movie_emb, x0);
    prep_bfrag<<<2, 256>>>(W1l, W1r, W2l, W2r);
    hist_kernel<<<(E + 255) / 256, 256>>>(edst, E);
    scan1_kernel<<<NBLK, SCAN_BS>>>();
    scan2_kernel<<<1, SCAN_BS>>>();
    scan3_kernel<<<NPAD / 256, 256>>>(E);
    fill_kernel<<<(E + 255) / 256, 256>>>(esrc, edst, E);

    // layer 1
    gather_mean<<<NPAD / 16, 256>>>(x0, mean);
    combine_mma<true><<<NTILES, 256>>>(x0, mean, bfh, bfl, b1, x1);

    // layer 2
    gather_mean<<<NPAD / 16, 256>>>(x1, mean);
    combine_mma<false><<<NTILES, 256>>>(x1, mean, bfh + 8192, bfl + 8192, b2, x0);

    // epilogue
    long long dot_threads = (long long)EL * 16;
    int dot_blocks = (int)((dot_threads + 255) / 256);
    edgedot_kernel<<<dot_blocks, 256>>>(x0, ell, ell + EL, out, EL);
}

// round 14
// speedup vs baseline: 2.3078x; 1.0386x over previous
#include <cuda_runtime.h>
#include <cuda_bf16.h>
#include <cstdint>

#define N_USERS 200000
#define N_MOVIES 80000
#define NN 280000
#define TILE_M 128
#define NTILES 2188                    // ceil(NN/128)
#define NPAD (NTILES * TILE_M)         // 280064
#define H 64
#define FM 20
#define EMAX 1310720                   // >= E (1250000)

#define SCAN_BS 256
#define SCAN_IT 8
#define SCAN_CHUNK (SCAN_BS * SCAN_IT)             // 2048
#define NBLK ((NPAD + SCAN_CHUNK - 1) / SCAN_CHUNK) // 137

typedef unsigned long long ull;

// Scratch (device globals; allocation is forbidden).
__device__ float g_x0[(size_t)NPAD * H];
__device__ float g_x1[(size_t)NPAD * H];
__device__ int g_cnt[NPAD];
__device__ int g_off[NPAD + 1];
__device__ int g_cur[NPAD];
__device__ int g_bsum[NBLK];
__device__ int g_csr[EMAX];
// Pre-built B fragments (bf16x2 words, mma.sync m16n8k16 layout), per layer.
__device__ uint32_t g_bfhi[2 * 8192];
__device__ uint32_t g_bflo[2 * 8192];

// ---------------- helpers ----------------
__device__ __forceinline__ uint16_t bf16_bits(float x) {
    __nv_bfloat16 b = __float2bfloat16(x);
    return *reinterpret_cast<uint16_t*>(&b);
}
__device__ __forceinline__ float bf16_val(uint16_t u) {
    __nv_bfloat16 b = *reinterpret_cast<__nv_bfloat16*>(&u);
    return __bfloat162float(b);
}
__device__ __forceinline__ uint32_t packbf(uint16_t lo, uint16_t hi) {
    return (uint32_t)lo | ((uint32_t)hi << 16);
}
// Truncation split of two fp32 into packed bf16x2 hi + bf16x2 lo.
__device__ __forceinline__ void split2(float2 v, uint32_t& hi, uint32_t& lo) {
    uint32_t bx = __float_as_uint(v.x), by = __float_as_uint(v.y);
    hi = __byte_perm(bx, by, 0x7632);
    float lx = v.x - __uint_as_float(bx & 0xFFFF0000u);
    float ly = v.y - __uint_as_float(by & 0xFFFF0000u);
    lo = __byte_perm(__float_as_uint(lx), __float_as_uint(ly), 0x7632);
}
__device__ __forceinline__ void mma_bf16(float* c, uint4 a, uint32_t b0, uint32_t b1) {
    asm volatile(
        "mma.sync.aligned.m16n8k16.row.col.f32.bf16.bf16.f32 "
        "{%0,%1,%2,%3}, {%4,%5,%6,%7}, {%8,%9}, {%0,%1,%2,%3};"
        : "+f"(c[0]), "+f"(c[1]), "+f"(c[2]), "+f"(c[3])
        : "r"(a.x), "r"(a.y), "r"(a.z), "r"(a.w), "r"(b0), "r"(b1));
}

// ---------------- B fragment prep ----------------
__global__ void prep_bfrag(const float* __restrict__ W1l, const float* __restrict__ W1r,
                           const float* __restrict__ W2l, const float* __restrict__ W2r) {
    int layer = blockIdx.x;
    const float* Wl = layer ? W2l : W1l;
    const float* Wr = layer ? W2r : W1r;
    uint32_t* BH = g_bfhi + layer * 8192;
    uint32_t* BL = g_bflo + layer * 8192;
    int t = threadIdx.x;
#pragma unroll
    for (int j = 0; j < 8; j++) {
        int idx = t + j * 256;
        int h = idx >> 5;
        int k0 = (idx & 31) * 4;
        float4 w4 = (k0 < 64)
            ? *reinterpret_cast<const float4*>(Wl + h * 64 + k0)
            : *reinterpret_cast<const float4*>(Wr + h * 64 + (k0 - 64));
        uint16_t h0 = bf16_bits(w4.x), h1 = bf16_bits(w4.y);
        uint16_t h2 = bf16_bits(w4.z), h3 = bf16_bits(w4.w);
        uint16_t l0 = bf16_bits(w4.x - bf16_val(h0));
        uint16_t l1 = bf16_bits(w4.y - bf16_val(h1));
        uint16_t l2 = bf16_bits(w4.z - bf16_val(h2));
        uint16_t l3 = bf16_bits(w4.w - bf16_val(h3));
        int kstep = k0 >> 4, kk = k0 & 15;
        int g = h & 7, nt = h >> 3;
        int w = nt * 2 + (kk >> 3);
        int lane01 = g * 4 + ((kk & 7) >> 1);
        int i01 = ((kstep * 4 + (w >> 2)) * 32 + lane01) * 4 + (w & 3);
        int i23 = i01 + 4;
        BH[i01] = packbf(h0, h1); BH[i23] = packbf(h2, h3);
        BL[i01] = packbf(l0, l1); BL[i23] = packbf(l2, l3);
    }
}

// ---------------- movie feature init ----------------
__global__ void movie_init_kernel(const float* __restrict__ movie_x,
                                  const float* __restrict__ lin_W,
                                  const float* __restrict__ lin_b,
                                  const float* __restrict__ movie_emb,
                                  float* __restrict__ x0) {
    int mlocal = threadIdx.x >> 6;
    int h = threadIdx.x & 63;
    int m = blockIdx.x * 4 + mlocal;
    __shared__ float mx[4][FM];
    int li = threadIdx.x;
    if (li < 4 * FM) {
        int mm = li / FM, ff = li % FM;
        mx[mm][ff] = movie_x[(size_t)(blockIdx.x * 4 + mm) * FM + ff];
    }
    __syncthreads();
    float s = lin_b[h];
#pragma unroll
    for (int f = 0; f < FM; f++) s += mx[mlocal][f] * lin_W[h * FM + f];
    x0[(size_t)(N_USERS + m) * H + h] = s + movie_emb[(size_t)m * H + h];
}

// ---------------- CSR build ----------------
__global__ void hist_kernel(const int* __restrict__ dst, int E) {
    int e = blockIdx.x * blockDim.x + threadIdx.x;
    if (e < E) atomicAdd(g_cnt + dst[e], 1);
}

__global__ void scan1_kernel() {
    __shared__ int sh[SCAN_BS];
    int b = blockIdx.x, t = threadIdx.x;
    int base = b * SCAN_CHUNK + t * SCAN_IT;
    int v[SCAN_IT];
    int tot = 0;
#pragma unroll
    for (int i = 0; i < SCAN_IT; i++) {
        int idx = base + i;
        v[i] = (idx < NPAD) ? g_cnt[idx] : 0;
        tot += v[i];
    }
    sh[t] = tot;
    __syncthreads();
    for (int off = 1; off < SCAN_BS; off <<= 1) {
        int val = (t >= off) ? sh[t - off] : 0;
        __syncthreads();
        sh[t] += val;
        __syncthreads();
    }
    int run = sh[t] - tot;   // exclusive prefix of this thread within block
#pragma unroll
    for (int i = 0; i < SCAN_IT; i++) {
        int idx = base + i;
        if (idx < NPAD) g_off[idx] = run;
        run += v[i];
    }
    if (t == SCAN_BS - 1) g_bsum[b] = sh[t];
}

__global__ void scan2_kernel() {
    __shared__ int sh[SCAN_BS];
    int t = threadIdx.x;
    int v = (t < NBLK) ? g_bsum[t] : 0;
    sh[t] = v;
    __syncthreads();
    for (int off = 1; off < SCAN_BS; off <<= 1) {
        int val = (t >= off) ? sh[t - off] : 0;
        __syncthreads();
        sh[t] += val;
        __syncthreads();
    }
    if (t < NBLK) g_bsum[t] = sh[t] - v;   // exclusive
}

__global__ void scan3_kernel(int E) {
    int i = blockIdx.x * blockDim.x + threadIdx.x;   // grid covers NPAD exactly
    int o = g_off[i] + g_bsum[i / SCAN_CHUNK];
    g_off[i] = o;
    g_cur[i] = o;
    if (i == 0) g_off[NPAD] = E;
}

__global__ void fill_kernel(const int* __restrict__ src, const int* __restrict__ dst, int E) {
    int e = blockIdx.x * blockDim.x + threadIdx.x;
    if (e >= E) return;
    int pos = atomicAdd(g_cur + dst[e], 1);
    g_csr[pos] = src[e];
}

// ---------------- fused gather + combine ----------------
// Phase 1: gather mean rows for this block's 128 nodes into swizzled smem.
// Phase 2: register-direct mma.sync, A = [mean(smem) | xin(global)], K=128.
// Swizzle: phys_float2(r, c2) = r*32 + (c2 ^ ((r*4)&31))  (conflict-free, 16B-aligned f4)
template <bool RELU>
__global__ void __launch_bounds__(256)
fused_combine(const float* __restrict__ xin,
              const uint32_t* __restrict__ BH,
              const uint32_t* __restrict__ BL,
              const float* __restrict__ bias,
              float* __restrict__ xout) {
    __shared__ float smean[128 * 64];
    int t = threadIdx.x;
    int rowBase = blockIdx.x * TILE_M;

    // ---- phase 1: gather ----
    int part = t & 15;
#pragma unroll 1
    for (int pass = 0; pass < 8; pass++) {
        int r = pass * 16 + (t >> 4);          // local row 0..127
        int node = rowBase + r;
        int o0 = g_off[node], o1 = g_off[node + 1];
        float4 acc = make_float4(0.f, 0.f, 0.f, 0.f);
        int e = o0;
        for (; e + 4 <= o1; e += 4) {
            int s0 = g_csr[e + 0];
            int s1 = g_csr[e + 1];
            int s2 = g_csr[e + 2];
            int s3 = g_csr[e + 3];
            float4 a0 = *reinterpret_cast<const float4*>(xin + (size_t)s0 * H + part * 4);
            float4 a1 = *reinterpret_cast<const float4*>(xin + (size_t)s1 * H + part * 4);
            float4 a2 = *reinterpret_cast<const float4*>(xin + (size_t)s2 * H + part * 4);
            float4 a3 = *reinterpret_cast<const float4*>(xin + (size_t)s3 * H + part * 4);
            acc.x += a0.x + a1.x + a2.x + a3.x;
            acc.y += a0.y + a1.y + a2.y + a3.y;
            acc.z += a0.z + a1.z + a2.z + a3.z;
            acc.w += a0.w + a1.w + a2.w + a3.w;
        }
        for (; e < o1; e++) {
            int s = g_csr[e];
            float4 v = *reinterpret_cast<const float4*>(xin + (size_t)s * H + part * 4);
            acc.x += v.x; acc.y += v.y; acc.z += v.z; acc.w += v.w;
        }
        float inv = 1.0f / fmaxf((float)(o1 - o0), 1.0f);
        acc.x *= inv; acc.y *= inv; acc.z *= inv; acc.w *= inv;
        int X = (r << 2) & 31;
        *reinterpret_cast<float4*>(smean + r * 64 + (((part * 2) ^ X) << 1)) = acc;
    }
    __syncthreads();

    // ---- phase 2: MMA ----
    int lane = t & 31, wid = t >> 5;
    int g = lane >> 2, t4 = lane & 3;
    int r0l = wid * 16 + g;                    // local rows
    int r1l = r0l + 8;
    int row0 = rowBase + r0l;
    int row1 = row0 + 8;
    int X = (r0l << 2) & 31;                   // same for r1l (+8 -> +32 mod 32)

    float acc[8][4];
#pragma unroll
    for (int n = 0; n < 8; n++)
#pragma unroll
        for (int i = 0; i < 4; i++) acc[n][i] = 0.f;

#pragma unroll
    for (int ks = 0; ks < 8; ks++) {
        float2 v00, v01, v10, v11;
        if (ks < 4) {
            int c2 = ks * 8 + t4;
            v00 = *reinterpret_cast<const float2*>(smean + r0l * 64 + ((c2 ^ X) << 1));
            v01 = *reinterpret_cast<const float2*>(smean + r0l * 64 + (((c2 + 4) ^ X) << 1));
            v10 = *reinterpret_cast<const float2*>(smean + r1l * 64 + ((c2 ^ X) << 1));
            v11 = *reinterpret_cast<const float2*>(smean + r1l * 64 + (((c2 + 4) ^ X) << 1));
        } else {
            int cc = (ks - 4) * 16 + t4 * 2;
            const float* p00 = xin + (size_t)row0 * H + cc;
            const float* p10 = xin + (size_t)row1 * H + cc;
            v00 = *reinterpret_cast<const float2*>(p00);
            v01 = *reinterpret_cast<const float2*>(p00 + 8);
            v10 = *reinterpret_cast<const float2*>(p10);
            v11 = *reinterpret_cast<const float2*>(p10 + 8);
        }

        const uint4* bh4 = reinterpret_cast<const uint4*>(BH) + (size_t)(ks * 4) * 32 + lane;
        const uint4* bl4 = reinterpret_cast<const uint4*>(BL) + (size_t)(ks * 4) * 32 + lane;
        uint4 bh[4], bl[4];
#pragma unroll
        for (int c = 0; c < 4; c++) { bh[c] = bh4[c * 32]; bl[c] = bl4[c * 32]; }

        uint4 ahi, alo;
        split2(v00, ahi.x, alo.x);
        split2(v10, ahi.y, alo.y);
        split2(v01, ahi.z, alo.z);
        split2(v11, ahi.w, alo.w);

        const uint32_t* bhw = reinterpret_cast<const uint32_t*>(bh);
        const uint32_t* blw = reinterpret_cast<const uint32_t*>(bl);
#pragma unroll
        for (int n = 0; n < 8; n++) {
            uint32_t b0h = bhw[n * 2], b1h = bhw[n * 2 + 1];
            mma_bf16(acc[n], ahi, b0h, b1h);
            mma_bf16(acc[n], alo, b0h, b1h);
            mma_bf16(acc[n], ahi, blw[n * 2], blw[n * 2 + 1]);
        }
    }

#pragma unroll
    for (int n = 0; n < 8; n++) {
        int c = n * 8 + t4 * 2;
        float2 b2 = *reinterpret_cast<const float2*>(bias + c);
        float o0 = acc[n][0] + b2.x, o1 = acc[n][1] + b2.y;
        float o2 = acc[n][2] + b2.x, o3 = acc[n][3] + b2.y;
        if (RELU) {
            o0 = fmaxf(o0, 0.f); o1 = fmaxf(o1, 0.f);
            o2 = fmaxf(o2, 0.f); o3 = fmaxf(o3, 0.f);
        }
        if (row0 < NN)
            *reinterpret_cast<float2*>(xout + (size_t)row0 * H + c) = make_float2(o0, o1);
        if (row1 < NN)
            *reinterpret_cast<float2*>(xout + (size_t)row1 * H + c) = make_float2(o2, o3);
    }
}

// ---------------- epilogue: out[e] = dot(x2[u], x2[N_USERS+m]) ----------------
__global__ void edgedot_kernel(const float* __restrict__ x2,
                               const int* __restrict__ lu,
                               const int* __restrict__ lm,
                               float* __restrict__ out, int EL) {
    long long t = (long long)blockIdx.x * blockDim.x + threadIdx.x;
    int e = (int)(t >> 4);
    if (e >= EL) return;
    int part = (int)t & 15;
    int u = lu[e];
    int m = lm[e];
    float4 a = *reinterpret_cast<const float4*>(x2 + (size_t)u * H + part * 4);
    float4 b = *reinterpret_cast<const float4*>(x2 + (size_t)(N_USERS + m) * H + part * 4);
    float s = a.x * b.x + a.y * b.y + a.z * b.z + a.w * b.w;
#pragma unroll
    for (int off = 8; off > 0; off >>= 1)
        s += __shfl_down_sync(0xffffffffu, s, off, 16);
    if (part == 0) out[e] = s;
}

extern "C" void kernel_launch(void* const* d_in, const int* in_sizes, int n_in,
                              void* d_out, int out_size) {
    const float* movie_x   = (const float*)d_in[0];
    const float* user_emb  = (const float*)d_in[1];
    const float* movie_emb = (const float*)d_in[2];
    const float* lin_W     = (const float*)d_in[3];
    const float* lin_b     = (const float*)d_in[4];
    const float* W1l       = (const float*)d_in[5];
    const float* b1        = (const float*)d_in[6];
    const float* W1r       = (const float*)d_in[7];
    const float* W2l       = (const float*)d_in[8];
    const float* b2        = (const float*)d_in[9];
    const float* W2r       = (const float*)d_in[10];
    const int* edge_index  = (const int*)d_in[11];   // int32: JAX x64 disabled
    const int* ell         = (const int*)d_in[12];
    int E  = in_sizes[11] / 2;
    int EL = in_sizes[12] / 2;
    float* out = (float*)d_out;

    float *x0, *x1;
    int *cnt;
    uint32_t *bfh, *bfl;
    cudaGetSymbolAddress((void**)&x0, g_x0);
    cudaGetSymbolAddress((void**)&x1, g_x1);
    cudaGetSymbolAddress((void**)&cnt, g_cnt);
    cudaGetSymbolAddress((void**)&bfh, g_bfhi);
    cudaGetSymbolAddress((void**)&bfl, g_bflo);

    const int* esrc = edge_index;
    const int* edst = edge_index + E;

    // init + CSR build
    cudaMemsetAsync(cnt, 0, sizeof(int) * NPAD);
    cudaMemcpyAsync(x0, user_emb, sizeof(float) * (size_t)N_USERS * H,
                    cudaMemcpyDeviceToDevice);
    movie_init_kernel<<<N_MOVIES / 4, 256>>>(movie_x, lin_W, lin_b, movie_emb, x0);
    prep_bfrag<<<2, 256>>>(W1l, W1r, W2l, W2r);
    hist_kernel<<<(E + 255) / 256, 256>>>(edst, E);
    scan1_kernel<<<NBLK, SCAN_BS>>>();
    scan2_kernel<<<1, SCAN_BS>>>();
    scan3_kernel<<<NPAD / 256, 256>>>(E);
    fill_kernel<<<(E + 255) / 256, 256>>>(esrc, edst, E);

    // layer 1 (gather fused into combine)
    fused_combine<true><<<NTILES, 256>>>(x0, bfh, bfl, b1, x1);

    // layer 2
    fused_combine<false><<<NTILES, 256>>>(x1, bfh + 8192, bfl + 8192, b2, x0);

    // epilogue
    long long dot_threads = (long long)EL * 16;
    int dot_blocks = (int)((dot_threads + 255) / 256);
    edgedot_kernel<<<dot_blocks, 256>>>(x0, ell, ell + EL, out, EL);
}

// round 15
// speedup vs baseline: 2.3635x; 1.0241x over previous
#include <cuda_runtime.h>
#include <cuda_bf16.h>
#include <cstdint>

#define N_USERS 200000
#define N_MOVIES 80000
#define NN 280000
#define TILE_M 128
#define NTILES 2188                    // ceil(NN/128)
#define NPAD (NTILES * TILE_M)         // 280064
#define H 64
#define FM 20
#define EMAX 1310720                   // >= E (1250000)

#define SCAN_BS 256
#define SCAN_IT 8
#define SCAN_CHUNK (SCAN_BS * SCAN_IT)             // 2048
#define NBLK ((NPAD + SCAN_CHUNK - 1) / SCAN_CHUNK) // 137

#define MOVIE_BLOCKS (N_MOVIES / 4)    // 20000
#define USER_F4 (N_USERS * H / 4)      // 3200000

typedef unsigned long long ull;

// Scratch (device globals; allocation is forbidden).
__device__ float g_x0[(size_t)NPAD * H];
__device__ float g_x1[(size_t)NPAD * H];
__device__ int g_cnt[NPAD];
__device__ int g_off[NPAD];            // block-local exclusive partials (scan1)
__device__ int g_cur[NPAD];
__device__ int g_bsum[NBLK];
__device__ int g_csr[EMAX];
// Pre-built B fragments (bf16x2 words, mma.sync m16n8k16 layout), per layer.
__device__ uint32_t g_bfhi[2 * 8192];
__device__ uint32_t g_bflo[2 * 8192];

// ---------------- helpers ----------------
__device__ __forceinline__ uint16_t bf16_bits(float x) {
    __nv_bfloat16 b = __float2bfloat16(x);
    return *reinterpret_cast<uint16_t*>(&b);
}
__device__ __forceinline__ float bf16_val(uint16_t u) {
    __nv_bfloat16 b = *reinterpret_cast<__nv_bfloat16*>(&u);
    return __bfloat162float(b);
}
__device__ __forceinline__ uint32_t packbf(uint16_t lo, uint16_t hi) {
    return (uint32_t)lo | ((uint32_t)hi << 16);
}
// Truncation split of two fp32 into packed bf16x2 hi + bf16x2 lo.
__device__ __forceinline__ void split2(float2 v, uint32_t& hi, uint32_t& lo) {
    uint32_t bx = __float_as_uint(v.x), by = __float_as_uint(v.y);
    hi = __byte_perm(bx, by, 0x7632);
    float lx = v.x - __uint_as_float(bx & 0xFFFF0000u);
    float ly = v.y - __uint_as_float(by & 0xFFFF0000u);
    lo = __byte_perm(__float_as_uint(lx), __float_as_uint(ly), 0x7632);
}
__device__ __forceinline__ void mma_bf16(float* c, uint4 a, uint32_t b0, uint32_t b1) {
    asm volatile(
        "mma.sync.aligned.m16n8k16.row.col.f32.bf16.bf16.f32 "
        "{%0,%1,%2,%3}, {%4,%5,%6,%7}, {%8,%9}, {%0,%1,%2,%3};"
        : "+f"(c[0]), "+f"(c[1]), "+f"(c[2]), "+f"(c[3])
        : "r"(a.x), "r"(a.y), "r"(a.z), "r"(a.w), "r"(b0), "r"(b1));
}

// ---------------- init: zero cnt/cur, copy user rows, movie rows, B-frag prep ----------------
__global__ void init_kernel(const float* __restrict__ movie_x,
                            const float* __restrict__ lin_W,
                            const float* __restrict__ lin_b,
                            const float* __restrict__ movie_emb,
                            const float* __restrict__ user_emb,
                            const float* __restrict__ W1l, const float* __restrict__ W1r,
                            const float* __restrict__ W2l, const float* __restrict__ W2r) {
    if (blockIdx.x >= MOVIE_BLOCKS) {
        // ---- B fragment prep (2 blocks, one per layer) ----
        int layer = blockIdx.x - MOVIE_BLOCKS;
        const float* Wl = layer ? W2l : W1l;
        const float* Wr = layer ? W2r : W1r;
        uint32_t* BH = g_bfhi + layer * 8192;
        uint32_t* BL = g_bflo + layer * 8192;
        int t = threadIdx.x;
#pragma unroll
        for (int j = 0; j < 8; j++) {
            int idx = t + j * 256;
            int h = idx >> 5;
            int k0 = (idx & 31) * 4;
            float4 w4 = (k0 < 64)
                ? *reinterpret_cast<const float4*>(Wl + h * 64 + k0)
                : *reinterpret_cast<const float4*>(Wr + h * 64 + (k0 - 64));
            uint16_t h0 = bf16_bits(w4.x), h1 = bf16_bits(w4.y);
            uint16_t h2 = bf16_bits(w4.z), h3 = bf16_bits(w4.w);
            uint16_t l0 = bf16_bits(w4.x - bf16_val(h0));
            uint16_t l1 = bf16_bits(w4.y - bf16_val(h1));
            uint16_t l2 = bf16_bits(w4.z - bf16_val(h2));
            uint16_t l3 = bf16_bits(w4.w - bf16_val(h3));
            int kstep = k0 >> 4, kk = k0 & 15;
            int g = h & 7, nt = h >> 3;
            int w = nt * 2 + (kk >> 3);
            int lane01 = g * 4 + ((kk & 7) >> 1);
            int i01 = ((kstep * 4 + (w >> 2)) * 32 + lane01) * 4 + (w & 3);
            int i23 = i01 + 4;
            BH[i01] = packbf(h0, h1); BH[i23] = packbf(h2, h3);
            BL[i01] = packbf(l0, l1); BL[i23] = packbf(l2, l3);
        }
        return;
    }

    int gtid = blockIdx.x * 256 + threadIdx.x;
    if (gtid < NPAD) { g_cnt[gtid] = 0; g_cur[gtid] = 0; }
    if (gtid < USER_F4)
        reinterpret_cast<float4*>(g_x0)[gtid] =
            reinterpret_cast<const float4*>(user_emb)[gtid];

    // ---- movie rows: x0[N_USERS+m] = movie_x[m]·lin_W.T + lin_b + movie_emb[m] ----
    int mlocal = threadIdx.x >> 6;
    int h = threadIdx.x & 63;
    int m = blockIdx.x * 4 + mlocal;
    __shared__ float mx[4][FM];
    int li = threadIdx.x;
    if (li < 4 * FM) {
        int mm = li / FM, ff = li % FM;
        mx[mm][ff] = movie_x[(size_t)(blockIdx.x * 4 + mm) * FM + ff];
    }
    __syncthreads();
    float s = lin_b[h];
#pragma unroll
    for (int f = 0; f < FM; f++) s += mx[mlocal][f] * lin_W[h * FM + f];
    g_x0[(size_t)(N_USERS + m) * H + h] = s + movie_emb[(size_t)m * H + h];
}

// ---------------- CSR build ----------------
__global__ void hist_kernel(const int* __restrict__ dst, int E) {
    int e = blockIdx.x * blockDim.x + threadIdx.x;
    if (e < E) atomicAdd(g_cnt + dst[e], 1);
}

__global__ void scan1_kernel() {
    __shared__ int sh[SCAN_BS];
    int b = blockIdx.x, t = threadIdx.x;
    int base = b * SCAN_CHUNK + t * SCAN_IT;
    int v[SCAN_IT];
    int tot = 0;
#pragma unroll
    for (int i = 0; i < SCAN_IT; i++) {
        int idx = base + i;
        v[i] = (idx < NPAD) ? g_cnt[idx] : 0;
        tot += v[i];
    }
    sh[t] = tot;
    __syncthreads();
    for (int off = 1; off < SCAN_BS; off <<= 1) {
        int val = (t >= off) ? sh[t - off] : 0;
        __syncthreads();
        sh[t] += val;
        __syncthreads();
    }
    int run = sh[t] - tot;   // exclusive prefix of this thread within block
#pragma unroll
    for (int i = 0; i < SCAN_IT; i++) {
        int idx = base + i;
        if (idx < NPAD) g_off[idx] = run;
        run += v[i];
    }
    if (t == SCAN_BS - 1) g_bsum[b] = sh[t];
}

__global__ void scan2_kernel() {
    __shared__ int sh[SCAN_BS];
    int t = threadIdx.x;
    int v = (t < NBLK) ? g_bsum[t] : 0;
    sh[t] = v;
    __syncthreads();
    for (int off = 1; off < SCAN_BS; off <<= 1) {
        int val = (t >= off) ? sh[t - off] : 0;
        __syncthreads();
        sh[t] += val;
        __syncthreads();
    }
    if (t < NBLK) g_bsum[t] = sh[t] - v;   // exclusive
}

// fill with offsets composed on the fly: base = off_partial[d] + bsum[chunk(d)]
__global__ void fill_kernel(const int* __restrict__ src, const int* __restrict__ dst, int E) {
    int e = blockIdx.x * blockDim.x + threadIdx.x;
    if (e >= E) return;
    int d = dst[e];
    int base = g_off[d] + g_bsum[d >> 11];
    int pos = base + atomicAdd(g_cur + d, 1);
    g_csr[pos] = src[e];
}

// ---------------- fused gather + combine ----------------
// Phase 1: gather mean rows for this block's 128 nodes into swizzled smem
//          (predicated 4-wide edge loop, no serial remainder).
// Phase 2: register-direct mma.sync, A = [mean(smem) | xin(global)], K=128.
// Swizzle: phys_float2(r, c2) = r*32 + (c2 ^ ((r*4)&31))
template <bool RELU>
__global__ void __launch_bounds__(256)
fused_combine(const float* __restrict__ xin,
              const uint32_t* __restrict__ BH,
              const uint32_t* __restrict__ BL,
              const float* __restrict__ bias,
              float* __restrict__ xout, int E) {
    __shared__ float smean[128 * 64];
    int t = threadIdx.x;
    int rowBase = blockIdx.x * TILE_M;

    // ---- phase 1: gather ----
    int part = t & 15;
    int O0[8], O1[8];
#pragma unroll
    for (int p = 0; p < 8; p++) {
        int node = rowBase + p * 16 + (t >> 4);
        O0[p] = g_off[node] + g_bsum[node >> 11];
        O1[p] = (node == NPAD - 1) ? E
              : g_off[node + 1] + g_bsum[(node + 1) >> 11];
    }
#pragma unroll
    for (int pass = 0; pass < 8; pass++) {
        int r = pass * 16 + (t >> 4);          // local row 0..127
        int o0 = O0[pass], o1 = O1[pass];
        float4 acc = make_float4(0.f, 0.f, 0.f, 0.f);
        for (int e = o0; e < o1; e += 4) {
            int e1 = min(e + 1, o1 - 1);
            int e2 = min(e + 2, o1 - 1);
            int e3 = min(e + 3, o1 - 1);
            int s0 = g_csr[e];
            int s1 = g_csr[e1];
            int s2 = g_csr[e2];
            int s3 = g_csr[e3];
            float4 a0 = *reinterpret_cast<const float4*>(xin + (size_t)s0 * H + part * 4);
            float4 a1 = *reinterpret_cast<const float4*>(xin + (size_t)s1 * H + part * 4);
            float4 a2 = *reinterpret_cast<const float4*>(xin + (size_t)s2 * H + part * 4);
            float4 a3 = *reinterpret_cast<const float4*>(xin + (size_t)s3 * H + part * 4);
            float w1 = (e + 1 < o1) ? 1.f : 0.f;
            float w2 = (e + 2 < o1) ? 1.f : 0.f;
            float w3 = (e + 3 < o1) ? 1.f : 0.f;
            acc.x += a0.x; acc.y += a0.y; acc.z += a0.z; acc.w += a0.w;
            acc.x = fmaf(w1, a1.x, acc.x); acc.y = fmaf(w1, a1.y, acc.y);
            acc.z = fmaf(w1, a1.z, acc.z); acc.w = fmaf(w1, a1.w, acc.w);
            acc.x = fmaf(w2, a2.x, acc.x); acc.y = fmaf(w2, a2.y, acc.y);
            acc.z = fmaf(w2, a2.z, acc.z); acc.w = fmaf(w2, a2.w, acc.w);
            acc.x = fmaf(w3, a3.x, acc.x); acc.y = fmaf(w3, a3.y, acc.y);
            acc.z = fmaf(w3, a3.z, acc.z); acc.w = fmaf(w3, a3.w, acc.w);
        }
        float inv = 1.0f / fmaxf((float)(o1 - o0), 1.0f);
        acc.x *= inv; acc.y *= inv; acc.z *= inv; acc.w *= inv;
        int X = (r << 2) & 31;
        *reinterpret_cast<float4*>(smean + r * 64 + (((part * 2) ^ X) << 1)) = acc;
    }
    __syncthreads();

    // ---- phase 2: MMA ----
    int lane = t & 31, wid = t >> 5;
    int g = lane >> 2, t4 = lane & 3;
    int r0l = wid * 16 + g;                    // local rows
    int r1l = r0l + 8;
    int row0 = rowBase + r0l;
    int row1 = row0 + 8;
    int X = (r0l << 2) & 31;                   // same for r1l (+8 -> +32 mod 32)

    float acc[8][4];
#pragma unroll
    for (int n = 0; n < 8; n++)
#pragma unroll
        for (int i = 0; i < 4; i++) acc[n][i] = 0.f;

#pragma unroll
    for (int ks = 0; ks < 8; ks++) {
        float2 v00, v01, v10, v11;
        if (ks < 4) {
            int c2 = ks * 8 + t4;
            v00 = *reinterpret_cast<const float2*>(smean + r0l * 64 + ((c2 ^ X) << 1));
            v01 = *reinterpret_cast<const float2*>(smean + r0l * 64 + (((c2 + 4) ^ X) << 1));
            v10 = *reinterpret_cast<const float2*>(smean + r1l * 64 + ((c2 ^ X) << 1));
            v11 = *reinterpret_cast<const float2*>(smean + r1l * 64 + (((c2 + 4) ^ X) << 1));
        } else {
            int cc = (ks - 4) * 16 + t4 * 2;
            const float* p00 = xin + (size_t)row0 * H + cc;
            const float* p10 = xin + (size_t)row1 * H + cc;
            v00 = *reinterpret_cast<const float2*>(p00);
            v01 = *reinterpret_cast<const float2*>(p00 + 8);
            v10 = *reinterpret_cast<const float2*>(p10);
            v11 = *reinterpret_cast<const float2*>(p10 + 8);
        }

        const uint4* bh4 = reinterpret_cast<const uint4*>(BH) + (size_t)(ks * 4) * 32 + lane;
        const uint4* bl4 = reinterpret_cast<const uint4*>(BL) + (size_t)(ks * 4) * 32 + lane;
        uint4 bh[4], bl[4];
#pragma unroll
        for (int c = 0; c < 4; c++) { bh[c] = bh4[c * 32]; bl[c] = bl4[c * 32]; }

        uint4 ahi, alo;
        split2(v00, ahi.x, alo.x);
        split2(v10, ahi.y, alo.y);
        split2(v01, ahi.z, alo.z);
        split2(v11, ahi.w, alo.w);

        const uint32_t* bhw = reinterpret_cast<const uint32_t*>(bh);
        const uint32_t* blw = reinterpret_cast<const uint32_t*>(bl);
#pragma unroll
        for (int n = 0; n < 8; n++) {
            uint32_t b0h = bhw[n * 2], b1h = bhw[n * 2 + 1];
            mma_bf16(acc[n], ahi, b0h, b1h);
            mma_bf16(acc[n], alo, b0h, b1h);
            mma_bf16(acc[n], ahi, blw[n * 2], blw[n * 2 + 1]);
        }
    }

#pragma unroll
    for (int n = 0; n < 8; n++) {
        int c = n * 8 + t4 * 2;
        float2 b2 = *reinterpret_cast<const float2*>(bias + c);
        float o0 = acc[n][0] + b2.x, o1 = acc[n][1] + b2.y;
        float o2 = acc[n][2] + b2.x, o3 = acc[n][3] + b2.y;
        if (RELU) {
            o0 = fmaxf(o0, 0.f); o1 = fmaxf(o1, 0.f);
            o2 = fmaxf(o2, 0.f); o3 = fmaxf(o3, 0.f);
        }
        if (row0 < NN)
            *reinterpret_cast<float2*>(xout + (size_t)row0 * H + c) = make_float2(o0, o1);
        if (row1 < NN)
            *reinterpret_cast<float2*>(xout + (size_t)row1 * H + c) = make_float2(o2, o3);
    }
}

// ---------------- epilogue: out[e] = dot(x2[u], x2[N_USERS+m]) ----------------
__global__ void edgedot_kernel(const float* __restrict__ x2,
                               const int* __restrict__ lu,
                               const int* __restrict__ lm,
                               float* __restrict__ out, int EL) {
    long long t = (long long)blockIdx.x * blockDim.x + threadIdx.x;
    int e = (int)(t >> 4);
    if (e >= EL) return;
    int part = (int)t & 15;
    int u = lu[e];
    int m = lm[e];
    float4 a = *reinterpret_cast<const float4*>(x2 + (size_t)u * H + part * 4);
    float4 b = *reinterpret_cast<const float4*>(x2 + (size_t)(N_USERS + m) * H + part * 4);
    float s = a.x * b.x + a.y * b.y + a.z * b.z + a.w * b.w;
#pragma unroll
    for (int off = 8; off > 0; off >>= 1)
        s += __shfl_down_sync(0xffffffffu, s, off, 16);
    if (part == 0) out[e] = s;
}

extern "C" void kernel_launch(void* const* d_in, const int* in_sizes, int n_in,
                              void* d_out, int out_size) {
    const float* movie_x   = (const float*)d_in[0];
    const float* user_emb  = (const float*)d_in[1];
    const float* movie_emb = (const float*)d_in[2];
    const float* lin_W     = (const float*)d_in[3];
    const float* lin_b     = (const float*)d_in[4];
    const float* W1l       = (const float*)d_in[5];
    const float* b1        = (const float*)d_in[6];
    const float* W1r       = (const float*)d_in[7];
    const float* W2l       = (const float*)d_in[8];
    const float* b2        = (const float*)d_in[9];
    const float* W2r       = (const float*)d_in[10];
    const int* edge_index  = (const int*)d_in[11];   // int32: JAX x64 disabled
    const int* ell         = (const int*)d_in[12];
    int E  = in_sizes[11] / 2;
    int EL = in_sizes[12] / 2;
    float* out = (float*)d_out;

    float *x0, *x1;
    uint32_t *bfh, *bfl;
    cudaGetSymbolAddress((void**)&x0, g_x0);
    cudaGetSymbolAddress((void**)&x1, g_x1);
    cudaGetSymbolAddress((void**)&bfh, g_bfhi);
    cudaGetSymbolAddress((void**)&bfl, g_bflo);

    const int* esrc = edge_index;
    const int* edst = edge_index + E;

    // 1: init (zero cnt/cur, user copy, movie rows, B-frag prep)
    init_kernel<<<MOVIE_BLOCKS + 2, 256>>>(movie_x, lin_W, lin_b, movie_emb,
                                           user_emb, W1l, W1r, W2l, W2r);
    // 2-5: CSR build
    hist_kernel<<<(E + 255) / 256, 256>>>(edst, E);
    scan1_kernel<<<NBLK, SCAN_BS>>>();
    scan2_kernel<<<1, SCAN_BS>>>();
    fill_kernel<<<(E + 255) / 256, 256>>>(esrc, edst, E);

    // 6: layer 1 (profiled slot)
    fused_combine<true><<<NTILES, 256>>>(x0, bfh, bfl, b1, x1, E);
    // 7: layer 2
    fused_combine<false><<<NTILES, 256>>>(x1, bfh + 8192, bfl + 8192, b2, x0, E);

    // 8: epilogue
    long long dot_threads = (long long)EL * 16;
    int dot_blocks = (int)((dot_threads + 255) / 256);
    edgedot_kernel<<<dot_blocks, 256>>>(x0, ell, ell + EL, out, EL);
}